// round 13
// baseline (speedup 1.0000x reference)
#include <cuda_runtime.h>
#include <cuda_bf16.h>
#include <math_constants.h>

#define B 32
#define HID 2048
#define D 128
#define NH 16
#define NKVH 8
#define NREP 2
#define BLKSZ 16
#define MAXBLK 128
#define CHUNK 128
#define NCHUNK 16
#define QKV_KS 16
#define WO_KS 32

typedef unsigned long long u64t;

// packed f32x2 fma: d = a*b + c elementwise on two packed floats
#define FMA2(d, a, b, c) \
    asm("fma.rn.f32x2 %0, %1, %2, %3;" : "=l"(d) : "l"(a), "l"(b), "l"(c))

__device__ __forceinline__ u64t pack2(float lo, float hi) {
    u64t r; asm("mov.b64 %0, {%1, %2};" : "=l"(r) : "f"(lo), "f"(hi)); return r;
}

// ---------------- scratch (no allocations allowed) ----------------
__device__ float g_qkvp[QKV_KS * B * 4096];        // qkv split-k partials
__device__ float g_q[B * NH * D];                  // post norm+rope q
__device__ float g_pacc[B * NH * NCHUNK * 128];    // per-chunk acc partials
__device__ float2 g_ml[B * NH * NCHUNK];           // per-chunk {m, l}
__device__ float g_attn[B * NH * D];               // attention output (pre-wo)
__device__ float g_opart[WO_KS * B * HID];         // wo split-k partials

// ---------------- kernel 1: qkv projection (split-k=16, f32x2) -----
// grid = (32 tiles of 128 cols, 16 k-slices of 128) = 512 CTAs, 256 thr.
__global__ void gemm_qkv_kernel(const float* __restrict__ X,
                                const float* __restrict__ Wq,
                                const float* __restrict__ Wk,
                                const float* __restrict__ Wv) {
    const int cg = threadIdx.x & 31;
    const int bg = threadIdx.x >> 5;
    const int gcol0 = blockIdx.x * 128 + cg * 4;
    const int ks = blockIdx.y;
    const int kbeg = ks * (HID / QKV_KS);   // 128-wide slice

    const float* W;
    int ldw, col0;
    if (gcol0 < 2048)      { W = Wq; ldw = 2048; col0 = gcol0; }
    else if (gcol0 < 3072) { W = Wk; ldw = 1024; col0 = gcol0 - 2048; }
    else                   { W = Wv; ldw = 1024; col0 = gcol0 - 3072; }

    __shared__ u64t sXd[32][64];   // x duplicated into both halves
    u64t acc01[4] = {0ull, 0ull, 0ull, 0ull};
    u64t acc23[4] = {0ull, 0ull, 0ull, 0ull};

    for (int kb = kbeg; kb < kbeg + HID / QKV_KS; kb += 64) {
        for (int i = threadIdx.x; i < 2048; i += 256) {
            int b = i >> 6, kk = i & 63;
            float x = X[b * HID + kb + kk];
            sXd[b][kk] = pack2(x, x);
        }
        __syncthreads();
        const float* wp = W + (long)kb * ldw + col0;
#pragma unroll 8
        for (int kk = 0; kk < 64; kk++) {
            ulonglong2 wv = *(const ulonglong2*)(wp + (long)kk * ldw);
#pragma unroll
            for (int j = 0; j < 4; j++) {
                u64t xx = sXd[bg * 4 + j][kk];
                FMA2(acc01[j], wv.x, xx, acc01[j]);
                FMA2(acc23[j], wv.y, xx, acc23[j]);
            }
        }
        __syncthreads();
    }
#pragma unroll
    for (int j = 0; j < 4; j++) {
        ulonglong2 r; r.x = acc01[j]; r.y = acc23[j];
        *(ulonglong2*)(g_qkvp + (long)ks * B * 4096 + (bg * 4 + j) * 4096 + gcol0) = r;
    }
}

// ---------------- kernel 2: reduce split-k + rmsnorm + rope --------
__global__ void norm_rope_kernel(const float* __restrict__ cosv,
                                 const float* __restrict__ sinv,
                                 const float* __restrict__ qw,
                                 const float* __restrict__ kw,
                                 float* __restrict__ out_k,
                                 float* __restrict__ out_v) {
    const int b = blockIdx.x;
    const int hh = blockIdx.y;
    const int d = threadIdx.x;

    int idx;
    if (hh < 16)       idx = b * 4096 + hh * 128 + d;
    else if (hh < 24)  idx = b * 4096 + 2048 + (hh - 16) * 128 + d;
    else               idx = b * 4096 + 3072 + (hh - 24) * 128 + d;

    float x = 0.f;
#pragma unroll
    for (int ks = 0; ks < QKV_KS; ks++) x += g_qkvp[(long)ks * B * 4096 + idx];

    if (hh >= 24) {
        out_v[(b * NKVH + (hh - 24)) * D + d] = x;
        return;
    }

    __shared__ float swarp[4];
    float s = x * x;
#pragma unroll
    for (int o = 16; o > 0; o >>= 1) s += __shfl_xor_sync(0xffffffffu, s, o);
    if ((d & 31) == 0) swarp[d >> 5] = s;
    __syncthreads();
    float tot = swarp[0] + swarp[1] + swarp[2] + swarp[3];
    float inv = rsqrtf(tot * (1.0f / 128.0f) + 1e-6f);
    float w = (hh < 16) ? qw[d] : kw[d];
    float y = x * inv * w;

    __shared__ float sy[128];
    sy[d] = y;
    __syncthreads();
    float rot = (d < 64) ? -sy[d + 64] : sy[d - 64];
    float o = y * cosv[b * D + d] + rot * sinv[b * D + d];

    if (hh < 16) g_q[(b * NH + hh) * D + d] = o;
    else         out_k[(b * NKVH + (hh - 16)) * D + d] = o;
}

// ---------------- kernel 3: attention partials (flash decode) ------
// grid.x = B*NKVH (256), grid.y = chunk (16). 128 threads = 4 warps,
// warp covers 32 positions (exactly 2 KV blocks), unroll x8.
// Software pipeline: K loads for iter i+1 issue during iter i's
// shfl/softmax phase; V loads deferred past the dot products.
__global__ void attn_partial_kernel(const float* __restrict__ k_cache,
                                    const float* __restrict__ v_cache,
                                    const int* __restrict__ block_tables,
                                    const int* __restrict__ context_lens) {
    const int b = blockIdx.x >> 3;
    const int kvh = blockIdx.x & 7;
    const int chunk = blockIdx.y;
    const int ctx = context_lens[b];
    const int p0 = chunk * CHUNK;
    if (p0 >= ctx) return;
    const int pend = min(p0 + CHUNK, ctx);

    const int w = threadIdx.x >> 5;
    const int l = threadIdx.x & 31;
    const int wstart = p0 + w * 32;          // 32-aligned
    const int cnt = max(0, min(wstart + 32, pend) - wstart);

    // resolve the (at most) two KV blocks this warp touches
    const int* bt = block_tables + b * MAXBLK;
    const int bi = wstart >> 4;              // 0..126 (even)
    const int blk0 = max(0, __ldg(bt + bi));
    const int blk1 = max(0, __ldg(bt + min(bi + 1, MAXBLK - 1)));
    const long hoff = (long)kvh * D + 4 * l;
    const float* kb0 = k_cache + (long)blk0 * BLKSZ * NKVH * D + hoff;
    const float* kb1 = k_cache + (long)blk1 * BLKSZ * NKVH * D + hoff;
    const float* vb0 = v_cache + (long)blk0 * BLKSZ * NKVH * D + hoff;
    const float* vb1 = v_cache + (long)blk1 * BLKSZ * NKVH * D + hoff;
    const int rowstride = NKVH * D;          // 1024 floats per position

    const int h0 = kvh * NREP;
    const float4 q0 = *(const float4*)(g_q + (b * NH + h0) * D + 4 * l);
    const float4 q1 = *(const float4*)(g_q + (b * NH + h0 + 1) * D + 4 * l);
    const float scale = 0.08838834764831845f;

    float m0 = -CUDART_INF_F, l0 = 0.f, m1 = -CUDART_INF_F, l1 = 0.f;
    float4 a0 = {0.f, 0.f, 0.f, 0.f}, a1 = {0.f, 0.f, 0.f, 0.f};

    const int cnt8 = cnt & ~7;
    float4 kcur[8];
    if (cnt8 > 0) {
        // prologue: K loads for the first iteration (i0 = 0, block 0)
#pragma unroll
        for (int j = 0; j < 8; j++)
            kcur[j] = *(const float4*)(kb0 + j * rowstride);
    }
    for (int i0 = 0; i0 < cnt8; i0 += 8) {
        const float* vb = (i0 < 16) ? vb0 : vb1;
        const int s0off = (i0 & 8);          // slot base within block
        // phase 1: dot products consume kcur (registers then dead)
        float s0v[8], s1v[8];
#pragma unroll
        for (int j = 0; j < 8; j++) {
            s0v[j] = q0.x * kcur[j].x + q0.y * kcur[j].y + q0.z * kcur[j].z + q0.w * kcur[j].w;
            s1v[j] = q1.x * kcur[j].x + q1.y * kcur[j].y + q1.z * kcur[j].z + q1.w * kcur[j].w;
        }
        // phase 2: V loads for this iter; latency hides under the shfl tree
        float4 vv[8];
#pragma unroll
        for (int j = 0; j < 8; j++)
            vv[j] = *(const float4*)(vb + (s0off + j) * rowstride);
        // phase 3: prefetch next iteration's K into kcur
        const int n0 = i0 + 8;
        if (n0 < cnt8) {
            const float* kbn = (n0 < 16) ? kb0 : kb1;
            const int snoff = (n0 & 8);
#pragma unroll
            for (int j = 0; j < 8; j++)
                kcur[j] = *(const float4*)(kbn + (snoff + j) * rowstride);
        }
        // phase 4: reduce + online softmax (covers V and next-K latency)
#pragma unroll
        for (int o = 16; o > 0; o >>= 1) {
#pragma unroll
            for (int j = 0; j < 8; j++) {
                s0v[j] += __shfl_xor_sync(0xffffffffu, s0v[j], o);
                s1v[j] += __shfl_xor_sync(0xffffffffu, s1v[j], o);
            }
        }
#pragma unroll
        for (int j = 0; j < 8; j++) {
            float s0 = s0v[j] * scale, s1 = s1v[j] * scale;
            float nm0 = fmaxf(m0, s0);
            float e0 = __expf(s0 - nm0);
            float f0 = __expf(m0 - nm0);
            l0 = l0 * f0 + e0;
            a0.x = a0.x * f0 + e0 * vv[j].x; a0.y = a0.y * f0 + e0 * vv[j].y;
            a0.z = a0.z * f0 + e0 * vv[j].z; a0.w = a0.w * f0 + e0 * vv[j].w;
            m0 = nm0;

            float nm1 = fmaxf(m1, s1);
            float e1 = __expf(s1 - nm1);
            float f1 = __expf(m1 - nm1);
            l1 = l1 * f1 + e1;
            a1.x = a1.x * f1 + e1 * vv[j].x; a1.y = a1.y * f1 + e1 * vv[j].y;
            a1.z = a1.z * f1 + e1 * vv[j].z; a1.w = a1.w * f1 + e1 * vv[j].w;
            m1 = nm1;
        }
    }
    for (int i = cnt8; i < cnt; i++) {
        const float* kb = (i < 16) ? kb0 : kb1;
        const float* vb = (i < 16) ? vb0 : vb1;
        float4 kv = *(const float4*)(kb + (i & 15) * rowstride);
        float4 vv = *(const float4*)(vb + (i & 15) * rowstride);
        float s0 = q0.x * kv.x + q0.y * kv.y + q0.z * kv.z + q0.w * kv.w;
        float s1 = q1.x * kv.x + q1.y * kv.y + q1.z * kv.z + q1.w * kv.w;
#pragma unroll
        for (int o = 16; o > 0; o >>= 1) {
            s0 += __shfl_xor_sync(0xffffffffu, s0, o);
            s1 += __shfl_xor_sync(0xffffffffu, s1, o);
        }
        s0 *= scale; s1 *= scale;
        float nm0 = fmaxf(m0, s0);
        float e0 = __expf(s0 - nm0);
        float f0 = __expf(m0 - nm0);
        l0 = l0 * f0 + e0;
        a0.x = a0.x * f0 + e0 * vv.x; a0.y = a0.y * f0 + e0 * vv.y;
        a0.z = a0.z * f0 + e0 * vv.z; a0.w = a0.w * f0 + e0 * vv.w;
        m0 = nm0;
        float nm1 = fmaxf(m1, s1);
        float e1 = __expf(s1 - nm1);
        float f1 = __expf(m1 - nm1);
        l1 = l1 * f1 + e1;
        a1.x = a1.x * f1 + e1 * vv.x; a1.y = a1.y * f1 + e1 * vv.y;
        a1.z = a1.z * f1 + e1 * vv.z; a1.w = a1.w * f1 + e1 * vv.w;
        m1 = nm1;
    }

    // combine 4 warps in smem
    __shared__ float sml[4][2][2];
    __shared__ float sacc[4][2][128];
    *(float4*)&sacc[w][0][4 * l] = a0;
    *(float4*)&sacc[w][1][4 * l] = a1;
    if (l == 0) {
        sml[w][0][0] = m0; sml[w][0][1] = l0;
        sml[w][1][0] = m1; sml[w][1][1] = l1;
    }
    __syncthreads();

    const int d = threadIdx.x;
#pragma unroll
    for (int h = 0; h < 2; h++) {
        float M = fmaxf(fmaxf(sml[0][h][0], sml[1][h][0]),
                        fmaxf(sml[2][h][0], sml[3][h][0]));
        float L = 0.f, A = 0.f;
#pragma unroll
        for (int ww = 0; ww < 4; ww++) {
            float f = __expf(sml[ww][h][0] - M);
            L += sml[ww][h][1] * f;
            A += sacc[ww][h][d] * f;
        }
        long hi = (long)(b * NH + h0 + h) * NCHUNK + chunk;
        g_pacc[hi * 128 + d] = A;
        if (d == 0) g_ml[hi] = make_float2(M, L);
    }
}

// ---------------- kernel 4: combine chunk partials -----------------
// m/l loads are 16 contiguous float2s (one 128B line, L1-broadcast).
__global__ void attn_combine_kernel(const int* __restrict__ context_lens) {
    const int b = blockIdx.x >> 4;
    const int h = blockIdx.x & 15;
    const int d = threadIdx.x;
    const int ctx = context_lens[b];
    const int nch = (ctx + CHUNK - 1) / CHUNK;

    const long base = (long)(b * NH + h) * NCHUNK;
    float mv[NCHUNK], lv[NCHUNK], av[NCHUNK];
#pragma unroll
    for (int c = 0; c < NCHUNK; c++) {
        float2 ml = g_ml[base + c];
        mv[c] = (c < nch) ? ml.x : -CUDART_INF_F;
        lv[c] = ml.y;
        av[c] = g_pacc[(base + c) * 128 + d];
    }
    float M = -CUDART_INF_F;
#pragma unroll
    for (int c = 0; c < NCHUNK; c++) M = fmaxf(M, mv[c]);
    float L = 0.f, A = 0.f;
#pragma unroll
    for (int c = 0; c < NCHUNK; c++) {
        float f = __expf(mv[c] - M);
        L += lv[c] * f;
        A += av[c] * f;
    }
    g_attn[(b * NH + h) * D + d] = A / L;
}

// ---------------- kernel 5: wo projection (split-k=32, f32x2) ------
// grid = (16 tiles of 128 cols, 32 ks of 64) = 512 CTAs, 256 threads.
__global__ void gemm_wo_kernel(const float* __restrict__ W) {
    const int cg = threadIdx.x & 31;
    const int bg = threadIdx.x >> 5;
    const int col0 = blockIdx.x * 128 + cg * 4;
    const int ks = blockIdx.y;
    const int kb = ks * (HID / WO_KS);   // one 64-wide slab

    __shared__ u64t sXd[32][64];
    for (int i = threadIdx.x; i < 2048; i += 256) {
        int b = i >> 6, kk = i & 63;
        float x = g_attn[b * HID + kb + kk];
        sXd[b][kk] = pack2(x, x);
    }

    u64t acc01[4] = {0ull, 0ull, 0ull, 0ull};
    u64t acc23[4] = {0ull, 0ull, 0ull, 0ull};

    __syncthreads();
    const float* wp = W + (long)kb * HID + col0;
#pragma unroll 8
    for (int kk = 0; kk < 64; kk++) {
        ulonglong2 wv = *(const ulonglong2*)(wp + (long)kk * HID);
#pragma unroll
        for (int j = 0; j < 4; j++) {
            u64t xx = sXd[bg * 4 + j][kk];
            FMA2(acc01[j], wv.x, xx, acc01[j]);
            FMA2(acc23[j], wv.y, xx, acc23[j]);
        }
    }
#pragma unroll
    for (int j = 0; j < 4; j++) {
        ulonglong2 r; r.x = acc01[j]; r.y = acc23[j];
        *(ulonglong2*)(g_opart + ((long)ks * B + bg * 4 + j) * HID + col0) = r;
    }
}

// ---------------- kernel 6: finalize output ------------------------
__global__ void finalize_kernel(float* __restrict__ out) {
    int i = blockIdx.x * blockDim.x + threadIdx.x;  // 16384 float4s
    float4 r = {0.f, 0.f, 0.f, 0.f};
#pragma unroll
    for (int ks = 0; ks < WO_KS; ks++) {
        float4 a = ((const float4*)(g_opart + (long)ks * B * HID))[i];
        r.x += a.x; r.y += a.y; r.z += a.z; r.w += a.w;
    }
    ((float4*)out)[i] = r;
}

// ---------------- launch ------------------------------------------
extern "C" void kernel_launch(void* const* d_in, const int* in_sizes, int n_in,
                              void* d_out, int out_size) {
    const float* hidden = (const float*)d_in[0];
    const float* cosv   = (const float*)d_in[1];
    const float* sinv   = (const float*)d_in[2];
    const float* kcache = (const float*)d_in[3];
    const float* vcache = (const float*)d_in[4];
    const float* wq     = (const float*)d_in[5];
    const float* wk     = (const float*)d_in[6];
    const float* wv     = (const float*)d_in[7];
    const float* wo     = (const float*)d_in[8];
    const float* qnw    = (const float*)d_in[9];
    const float* knw    = (const float*)d_in[10];
    const int*   btab   = (const int*)d_in[11];
    const int*   clens  = (const int*)d_in[12];

    float* out    = (float*)d_out;
    float* out_k  = out + B * HID;
    float* out_v  = out_k + B * NKVH * D;

    gemm_qkv_kernel<<<dim3(32, QKV_KS), 256>>>(hidden, wq, wk, wv);
    norm_rope_kernel<<<dim3(B, 32), 128>>>(cosv, sinv, qnw, knw, out_k, out_v);
    attn_partial_kernel<<<dim3(B * NKVH, NCHUNK), 128>>>(kcache, vcache, btab, clens);
    attn_combine_kernel<<<B * NH, 128>>>(clens);
    gemm_wo_kernel<<<dim3(16, WO_KS), 256>>>(wo);
    finalize_kernel<<<64, 256>>>(out);
}

// round 14
// speedup vs baseline: 1.0021x; 1.0021x over previous
#include <cuda_runtime.h>
#include <cuda_bf16.h>
#include <math_constants.h>

#define B 32
#define HID 2048
#define D 128
#define NH 16
#define NKVH 8
#define NREP 2
#define BLKSZ 16
#define MAXBLK 128
#define CHUNK 128
#define NCHUNK 16
#define QKV_KS 16
#define WO_KS 32

typedef unsigned long long u64t;

// packed f32x2 fma: d = a*b + c elementwise on two packed floats
#define FMA2(d, a, b, c) \
    asm("fma.rn.f32x2 %0, %1, %2, %3;" : "=l"(d) : "l"(a), "l"(b), "l"(c))

__device__ __forceinline__ u64t pack2(float lo, float hi) {
    u64t r; asm("mov.b64 %0, {%1, %2};" : "=l"(r) : "f"(lo), "f"(hi)); return r;
}

// ---------------- scratch (no allocations allowed) ----------------
__device__ float g_qkvp[QKV_KS * B * 4096];        // qkv split-k partials
__device__ float g_q[B * NH * D];                  // post norm+rope q
__device__ float g_pacc[B * NH * NCHUNK * 128];    // per-chunk acc partials
__device__ float2 g_ml[B * NH * NCHUNK];           // per-chunk {m, l}
__device__ float g_attn[B * NH * D];               // attention output (pre-wo)
__device__ float g_opart[WO_KS * B * HID];         // wo split-k partials
__device__ int   g_sync[B * NKVH];                 // last-CTA counters (zero-init; reset after use)

// ---------------- kernel 1: qkv projection (split-k=16, f32x2) -----
// grid = (32 tiles of 128 cols, 16 k-slices of 128) = 512 CTAs, 256 thr.
__global__ void gemm_qkv_kernel(const float* __restrict__ X,
                                const float* __restrict__ Wq,
                                const float* __restrict__ Wk,
                                const float* __restrict__ Wv) {
    const int cg = threadIdx.x & 31;
    const int bg = threadIdx.x >> 5;
    const int gcol0 = blockIdx.x * 128 + cg * 4;
    const int ks = blockIdx.y;
    const int kbeg = ks * (HID / QKV_KS);   // 128-wide slice

    const float* W;
    int ldw, col0;
    if (gcol0 < 2048)      { W = Wq; ldw = 2048; col0 = gcol0; }
    else if (gcol0 < 3072) { W = Wk; ldw = 1024; col0 = gcol0 - 2048; }
    else                   { W = Wv; ldw = 1024; col0 = gcol0 - 3072; }

    __shared__ u64t sXd[32][64];   // x duplicated into both halves
    u64t acc01[4] = {0ull, 0ull, 0ull, 0ull};
    u64t acc23[4] = {0ull, 0ull, 0ull, 0ull};

    for (int kb = kbeg; kb < kbeg + HID / QKV_KS; kb += 64) {
        for (int i = threadIdx.x; i < 2048; i += 256) {
            int b = i >> 6, kk = i & 63;
            float x = X[b * HID + kb + kk];
            sXd[b][kk] = pack2(x, x);
        }
        __syncthreads();
        const float* wp = W + (long)kb * ldw + col0;
#pragma unroll 8
        for (int kk = 0; kk < 64; kk++) {
            ulonglong2 wv = *(const ulonglong2*)(wp + (long)kk * ldw);
#pragma unroll
            for (int j = 0; j < 4; j++) {
                u64t xx = sXd[bg * 4 + j][kk];
                FMA2(acc01[j], wv.x, xx, acc01[j]);
                FMA2(acc23[j], wv.y, xx, acc23[j]);
            }
        }
        __syncthreads();
    }
#pragma unroll
    for (int j = 0; j < 4; j++) {
        ulonglong2 r; r.x = acc01[j]; r.y = acc23[j];
        *(ulonglong2*)(g_qkvp + (long)ks * B * 4096 + (bg * 4 + j) * 4096 + gcol0) = r;
    }
}

// ---------------- kernel 2: reduce split-k + rmsnorm + rope --------
__global__ void norm_rope_kernel(const float* __restrict__ cosv,
                                 const float* __restrict__ sinv,
                                 const float* __restrict__ qw,
                                 const float* __restrict__ kw,
                                 float* __restrict__ out_k,
                                 float* __restrict__ out_v) {
    const int b = blockIdx.x;
    const int hh = blockIdx.y;
    const int d = threadIdx.x;

    int idx;
    if (hh < 16)       idx = b * 4096 + hh * 128 + d;
    else if (hh < 24)  idx = b * 4096 + 2048 + (hh - 16) * 128 + d;
    else               idx = b * 4096 + 3072 + (hh - 24) * 128 + d;

    float x = 0.f;
#pragma unroll
    for (int ks = 0; ks < QKV_KS; ks++) x += g_qkvp[(long)ks * B * 4096 + idx];

    if (hh >= 24) {
        out_v[(b * NKVH + (hh - 24)) * D + d] = x;
        return;
    }

    __shared__ float swarp[4];
    float s = x * x;
#pragma unroll
    for (int o = 16; o > 0; o >>= 1) s += __shfl_xor_sync(0xffffffffu, s, o);
    if ((d & 31) == 0) swarp[d >> 5] = s;
    __syncthreads();
    float tot = swarp[0] + swarp[1] + swarp[2] + swarp[3];
    float inv = rsqrtf(tot * (1.0f / 128.0f) + 1e-6f);
    float w = (hh < 16) ? qw[d] : kw[d];
    float y = x * inv * w;

    __shared__ float sy[128];
    sy[d] = y;
    __syncthreads();
    float rot = (d < 64) ? -sy[d + 64] : sy[d - 64];
    float o = y * cosv[b * D + d] + rot * sinv[b * D + d];

    if (hh < 16) g_q[(b * NH + hh) * D + d] = o;
    else         out_k[(b * NKVH + (hh - 16)) * D + d] = o;
}

// ---------------- kernel 3: attention partials + fused combine -----
// grid.x = B*NKVH (256), grid.y = chunk (16). 128 threads = 4 warps,
// warp covers 32 positions (exactly 2 KV blocks), unroll x8.
// K loads first; V loads deferred. Last-arriving CTA per (b,kvh)
// performs the cross-chunk softmax combine (threadFenceReduction).
__global__ void attn_partial_kernel(const float* __restrict__ k_cache,
                                    const float* __restrict__ v_cache,
                                    const int* __restrict__ block_tables,
                                    const int* __restrict__ context_lens) {
    const int b = blockIdx.x >> 3;
    const int kvh = blockIdx.x & 7;
    const int chunk = blockIdx.y;
    const int ctx = context_lens[b];
    const int p0 = chunk * CHUNK;
    if (p0 >= ctx) return;
    const int pend = min(p0 + CHUNK, ctx);
    const int nch = (ctx + CHUNK - 1) / CHUNK;

    const int w = threadIdx.x >> 5;
    const int l = threadIdx.x & 31;
    const int wstart = p0 + w * 32;          // 32-aligned
    const int cnt = max(0, min(wstart + 32, pend) - wstart);

    // resolve the (at most) two KV blocks this warp touches
    const int* bt = block_tables + b * MAXBLK;
    const int bi = wstart >> 4;              // 0..126 (even)
    const int blk0 = max(0, __ldg(bt + bi));
    const int blk1 = max(0, __ldg(bt + min(bi + 1, MAXBLK - 1)));
    const long hoff = (long)kvh * D + 4 * l;
    const float* kb0 = k_cache + (long)blk0 * BLKSZ * NKVH * D + hoff;
    const float* kb1 = k_cache + (long)blk1 * BLKSZ * NKVH * D + hoff;
    const float* vb0 = v_cache + (long)blk0 * BLKSZ * NKVH * D + hoff;
    const float* vb1 = v_cache + (long)blk1 * BLKSZ * NKVH * D + hoff;
    const int rowstride = NKVH * D;          // 1024 floats per position

    const int h0 = kvh * NREP;
    const float4 q0 = *(const float4*)(g_q + (b * NH + h0) * D + 4 * l);
    const float4 q1 = *(const float4*)(g_q + (b * NH + h0 + 1) * D + 4 * l);
    const float scale = 0.08838834764831845f;

    float m0 = -CUDART_INF_F, l0 = 0.f, m1 = -CUDART_INF_F, l1 = 0.f;
    float4 a0 = {0.f, 0.f, 0.f, 0.f}, a1 = {0.f, 0.f, 0.f, 0.f};

    const int cnt8 = cnt & ~7;
    for (int i0 = 0; i0 < cnt8; i0 += 8) {
        const float* kb = (i0 < 16) ? kb0 : kb1;
        const float* vb = (i0 < 16) ? vb0 : vb1;
        const int s0off = (i0 & 8);          // slot base within block
        // phase 1: K loads + dot products
        float4 kv[8];
#pragma unroll
        for (int j = 0; j < 8; j++)
            kv[j] = *(const float4*)(kb + (s0off + j) * rowstride);
        float s0v[8], s1v[8];
#pragma unroll
        for (int j = 0; j < 8; j++) {
            s0v[j] = q0.x * kv[j].x + q0.y * kv[j].y + q0.z * kv[j].z + q0.w * kv[j].w;
            s1v[j] = q1.x * kv[j].x + q1.y * kv[j].y + q1.z * kv[j].z + q1.w * kv[j].w;
        }
        // phase 2: V loads issued now; latency hides under the shfl tree
        float4 vv[8];
#pragma unroll
        for (int j = 0; j < 8; j++)
            vv[j] = *(const float4*)(vb + (s0off + j) * rowstride);
#pragma unroll
        for (int o = 16; o > 0; o >>= 1) {
#pragma unroll
            for (int j = 0; j < 8; j++) {
                s0v[j] += __shfl_xor_sync(0xffffffffu, s0v[j], o);
                s1v[j] += __shfl_xor_sync(0xffffffffu, s1v[j], o);
            }
        }
#pragma unroll
        for (int j = 0; j < 8; j++) {
            float s0 = s0v[j] * scale, s1 = s1v[j] * scale;
            float nm0 = fmaxf(m0, s0);
            float e0 = __expf(s0 - nm0);
            float f0 = __expf(m0 - nm0);
            l0 = l0 * f0 + e0;
            a0.x = a0.x * f0 + e0 * vv[j].x; a0.y = a0.y * f0 + e0 * vv[j].y;
            a0.z = a0.z * f0 + e0 * vv[j].z; a0.w = a0.w * f0 + e0 * vv[j].w;
            m0 = nm0;

            float nm1 = fmaxf(m1, s1);
            float e1 = __expf(s1 - nm1);
            float f1 = __expf(m1 - nm1);
            l1 = l1 * f1 + e1;
            a1.x = a1.x * f1 + e1 * vv[j].x; a1.y = a1.y * f1 + e1 * vv[j].y;
            a1.z = a1.z * f1 + e1 * vv[j].z; a1.w = a1.w * f1 + e1 * vv[j].w;
            m1 = nm1;
        }
    }
    for (int i = cnt8; i < cnt; i++) {
        const float* kb = (i < 16) ? kb0 : kb1;
        const float* vb = (i < 16) ? vb0 : vb1;
        float4 kv = *(const float4*)(kb + (i & 15) * rowstride);
        float4 vv = *(const float4*)(vb + (i & 15) * rowstride);
        float s0 = q0.x * kv.x + q0.y * kv.y + q0.z * kv.z + q0.w * kv.w;
        float s1 = q1.x * kv.x + q1.y * kv.y + q1.z * kv.z + q1.w * kv.w;
#pragma unroll
        for (int o = 16; o > 0; o >>= 1) {
            s0 += __shfl_xor_sync(0xffffffffu, s0, o);
            s1 += __shfl_xor_sync(0xffffffffu, s1, o);
        }
        s0 *= scale; s1 *= scale;
        float nm0 = fmaxf(m0, s0);
        float e0 = __expf(s0 - nm0);
        float f0 = __expf(m0 - nm0);
        l0 = l0 * f0 + e0;
        a0.x = a0.x * f0 + e0 * vv.x; a0.y = a0.y * f0 + e0 * vv.y;
        a0.z = a0.z * f0 + e0 * vv.z; a0.w = a0.w * f0 + e0 * vv.w;
        m0 = nm0;
        float nm1 = fmaxf(m1, s1);
        float e1 = __expf(s1 - nm1);
        float f1 = __expf(m1 - nm1);
        l1 = l1 * f1 + e1;
        a1.x = a1.x * f1 + e1 * vv.x; a1.y = a1.y * f1 + e1 * vv.y;
        a1.z = a1.z * f1 + e1 * vv.z; a1.w = a1.w * f1 + e1 * vv.w;
        m1 = nm1;
    }

    // combine 4 warps in smem
    __shared__ float sml[4][2][2];
    __shared__ float sacc[4][2][128];
    *(float4*)&sacc[w][0][4 * l] = a0;
    *(float4*)&sacc[w][1][4 * l] = a1;
    if (l == 0) {
        sml[w][0][0] = m0; sml[w][0][1] = l0;
        sml[w][1][0] = m1; sml[w][1][1] = l1;
    }
    __syncthreads();

    const int d = threadIdx.x;
#pragma unroll
    for (int h = 0; h < 2; h++) {
        float M = fmaxf(fmaxf(sml[0][h][0], sml[1][h][0]),
                        fmaxf(sml[2][h][0], sml[3][h][0]));
        float L = 0.f, A = 0.f;
#pragma unroll
        for (int ww = 0; ww < 4; ww++) {
            float f = __expf(sml[ww][h][0] - M);
            L += sml[ww][h][1] * f;
            A += sacc[ww][h][d] * f;
        }
        long hi = (long)(b * NH + h0 + h) * NCHUNK + chunk;
        g_pacc[hi * 128 + d] = A;
        if (d == 0) g_ml[hi] = make_float2(M, L);
    }

    // ---- fused cross-chunk combine: last-arriving CTA does it ----
    __threadfence();                          // publish partials
    __shared__ int s_last;
    if (d == 0) {
        int old = atomicAdd(&g_sync[blockIdx.x], 1);
        int last = (old == nch - 1);
        if (last) g_sync[blockIdx.x] = 0;     // reset for next graph replay
        s_last = last;
    }
    __syncthreads();
    if (!s_last) return;
    __threadfence();                          // acquire other CTAs' partials

#pragma unroll
    for (int h = 0; h < 2; h++) {
        const long base = (long)(b * NH + h0 + h) * NCHUNK;
        float mv[NCHUNK], lv[NCHUNK], av[NCHUNK];
#pragma unroll
        for (int c = 0; c < NCHUNK; c++) {
            float2 ml = g_ml[base + c];
            mv[c] = (c < nch) ? ml.x : -CUDART_INF_F;
            lv[c] = ml.y;
            av[c] = g_pacc[(base + c) * 128 + d];
        }
        float M = -CUDART_INF_F;
#pragma unroll
        for (int c = 0; c < NCHUNK; c++) M = fmaxf(M, mv[c]);
        float L = 0.f, A = 0.f;
#pragma unroll
        for (int c = 0; c < NCHUNK; c++) {
            float f = __expf(mv[c] - M);
            L += lv[c] * f;
            A += av[c] * f;
        }
        g_attn[(b * NH + h0 + h) * D + d] = A / L;
    }
}

// ---------------- kernel 4: wo projection (split-k=32, f32x2) ------
// grid = (16 tiles of 128 cols, 32 ks of 64) = 512 CTAs, 256 threads.
__global__ void gemm_wo_kernel(const float* __restrict__ W) {
    const int cg = threadIdx.x & 31;
    const int bg = threadIdx.x >> 5;
    const int col0 = blockIdx.x * 128 + cg * 4;
    const int ks = blockIdx.y;
    const int kb = ks * (HID / WO_KS);   // one 64-wide slab

    __shared__ u64t sXd[32][64];
    for (int i = threadIdx.x; i < 2048; i += 256) {
        int b = i >> 6, kk = i & 63;
        float x = g_attn[b * HID + kb + kk];
        sXd[b][kk] = pack2(x, x);
    }

    u64t acc01[4] = {0ull, 0ull, 0ull, 0ull};
    u64t acc23[4] = {0ull, 0ull, 0ull, 0ull};

    __syncthreads();
    const float* wp = W + (long)kb * HID + col0;
#pragma unroll 8
    for (int kk = 0; kk < 64; kk++) {
        ulonglong2 wv = *(const ulonglong2*)(wp + (long)kk * HID);
#pragma unroll
        for (int j = 0; j < 4; j++) {
            u64t xx = sXd[bg * 4 + j][kk];
            FMA2(acc01[j], wv.x, xx, acc01[j]);
            FMA2(acc23[j], wv.y, xx, acc23[j]);
        }
    }
#pragma unroll
    for (int j = 0; j < 4; j++) {
        ulonglong2 r; r.x = acc01[j]; r.y = acc23[j];
        *(ulonglong2*)(g_opart + ((long)ks * B + bg * 4 + j) * HID + col0) = r;
    }
}

// ---------------- kernel 5: finalize output ------------------------
__global__ void finalize_kernel(float* __restrict__ out) {
    int i = blockIdx.x * blockDim.x + threadIdx.x;  // 16384 float4s
    float4 r = {0.f, 0.f, 0.f, 0.f};
#pragma unroll
    for (int ks = 0; ks < WO_KS; ks++) {
        float4 a = ((const float4*)(g_opart + (long)ks * B * HID))[i];
        r.x += a.x; r.y += a.y; r.z += a.z; r.w += a.w;
    }
    ((float4*)out)[i] = r;
}

// ---------------- launch ------------------------------------------
extern "C" void kernel_launch(void* const* d_in, const int* in_sizes, int n_in,
                              void* d_out, int out_size) {
    const float* hidden = (const float*)d_in[0];
    const float* cosv   = (const float*)d_in[1];
    const float* sinv   = (const float*)d_in[2];
    const float* kcache = (const float*)d_in[3];
    const float* vcache = (const float*)d_in[4];
    const float* wq     = (const float*)d_in[5];
    const float* wk     = (const float*)d_in[6];
    const float* wv     = (const float*)d_in[7];
    const float* wo     = (const float*)d_in[8];
    const float* qnw    = (const float*)d_in[9];
    const float* knw    = (const float*)d_in[10];
    const int*   btab   = (const int*)d_in[11];
    const int*   clens  = (const int*)d_in[12];

    float* out    = (float*)d_out;
    float* out_k  = out + B * HID;
    float* out_v  = out_k + B * NKVH * D;

    gemm_qkv_kernel<<<dim3(32, QKV_KS), 256>>>(hidden, wq, wk, wv);
    norm_rope_kernel<<<dim3(B, 32), 128>>>(cosv, sinv, qnw, knw, out_k, out_v);
    attn_partial_kernel<<<dim3(B * NKVH, NCHUNK), 128>>>(kcache, vcache, btab, clens);
    gemm_wo_kernel<<<dim3(16, WO_KS), 256>>>(wo);
    finalize_kernel<<<64, 256>>>(out);
}

// round 15
// speedup vs baseline: 1.0027x; 1.0006x over previous
#include <cuda_runtime.h>
#include <cuda_bf16.h>
#include <math_constants.h>

#define B 32
#define HID 2048
#define D 128
#define NH 16
#define NKVH 8
#define NREP 2
#define BLKSZ 16
#define MAXBLK 128
#define CHUNK 128
#define NCHUNK 16
#define QKV_KS 16
#define WO_KS 32

typedef unsigned long long u64t;

// packed f32x2 fma: d = a*b + c elementwise on two packed floats
#define FMA2(d, a, b, c) \
    asm("fma.rn.f32x2 %0, %1, %2, %3;" : "=l"(d) : "l"(a), "l"(b), "l"(c))

__device__ __forceinline__ u64t pack2(float lo, float hi) {
    u64t r; asm("mov.b64 %0, {%1, %2};" : "=l"(r) : "f"(lo), "f"(hi)); return r;
}

// ---------------- scratch (no allocations allowed) ----------------
__device__ float g_qkvp[QKV_KS * B * 4096];        // qkv split-k partials
__device__ float g_q[B * NH * D];                  // post norm+rope q
__device__ float g_pacc[B * NH * NCHUNK * 128];    // per-chunk acc partials
__device__ float2 g_ml[B * NH * NCHUNK];           // per-chunk {m, l}
__device__ float g_attn[B * NH * D];               // attention output (pre-wo)
__device__ float g_opart[WO_KS * B * HID];         // wo split-k partials

// ---------------- kernel 1: qkv projection (split-k=16, f32x2) -----
// grid = (32 tiles of 128 cols, 16 k-slices of 128) = 512 CTAs, 256 thr.
// Warps stagger their k-order (offset bg*8) so the CTA keeps 64 DISTINCT
// W lines in flight instead of 8 duplicate groups.
__global__ void gemm_qkv_kernel(const float* __restrict__ X,
                                const float* __restrict__ Wq,
                                const float* __restrict__ Wk,
                                const float* __restrict__ Wv) {
    const int cg = threadIdx.x & 31;
    const int bg = threadIdx.x >> 5;
    const int gcol0 = blockIdx.x * 128 + cg * 4;
    const int ks = blockIdx.y;
    const int kbeg = ks * (HID / QKV_KS);   // 128-wide slice

    const float* W;
    int ldw, col0;
    if (gcol0 < 2048)      { W = Wq; ldw = 2048; col0 = gcol0; }
    else if (gcol0 < 3072) { W = Wk; ldw = 1024; col0 = gcol0 - 2048; }
    else                   { W = Wv; ldw = 1024; col0 = gcol0 - 3072; }

    __shared__ u64t sXd[32][64];   // x duplicated into both halves
    u64t acc01[4] = {0ull, 0ull, 0ull, 0ull};
    u64t acc23[4] = {0ull, 0ull, 0ull, 0ull};

    const int rot = bg * 8;        // per-warp k-order stagger

    for (int kb = kbeg; kb < kbeg + HID / QKV_KS; kb += 64) {
        for (int i = threadIdx.x; i < 2048; i += 256) {
            int b = i >> 6, kk = i & 63;
            float x = X[b * HID + kb + kk];
            sXd[b][kk] = pack2(x, x);
        }
        __syncthreads();
        const float* wp = W + (long)kb * ldw + col0;
#pragma unroll 8
        for (int kkx = 0; kkx < 64; kkx++) {
            int kk = (kkx + rot) & 63;
            ulonglong2 wv = *(const ulonglong2*)(wp + (long)kk * ldw);
#pragma unroll
            for (int j = 0; j < 4; j++) {
                u64t xx = sXd[bg * 4 + j][kk];
                FMA2(acc01[j], wv.x, xx, acc01[j]);
                FMA2(acc23[j], wv.y, xx, acc23[j]);
            }
        }
        __syncthreads();
    }
#pragma unroll
    for (int j = 0; j < 4; j++) {
        ulonglong2 r; r.x = acc01[j]; r.y = acc23[j];
        *(ulonglong2*)(g_qkvp + (long)ks * B * 4096 + (bg * 4 + j) * 4096 + gcol0) = r;
    }
}

// ---------------- kernel 2: reduce split-k + rmsnorm + rope --------
__global__ void norm_rope_kernel(const float* __restrict__ cosv,
                                 const float* __restrict__ sinv,
                                 const float* __restrict__ qw,
                                 const float* __restrict__ kw,
                                 float* __restrict__ out_k,
                                 float* __restrict__ out_v) {
    const int b = blockIdx.x;
    const int hh = blockIdx.y;
    const int d = threadIdx.x;

    int idx;
    if (hh < 16)       idx = b * 4096 + hh * 128 + d;
    else if (hh < 24)  idx = b * 4096 + 2048 + (hh - 16) * 128 + d;
    else               idx = b * 4096 + 3072 + (hh - 24) * 128 + d;

    float x = 0.f;
#pragma unroll
    for (int ks = 0; ks < QKV_KS; ks++) x += g_qkvp[(long)ks * B * 4096 + idx];

    if (hh >= 24) {
        out_v[(b * NKVH + (hh - 24)) * D + d] = x;
        return;
    }

    __shared__ float swarp[4];
    float s = x * x;
#pragma unroll
    for (int o = 16; o > 0; o >>= 1) s += __shfl_xor_sync(0xffffffffu, s, o);
    if ((d & 31) == 0) swarp[d >> 5] = s;
    __syncthreads();
    float tot = swarp[0] + swarp[1] + swarp[2] + swarp[3];
    float inv = rsqrtf(tot * (1.0f / 128.0f) + 1e-6f);
    float w = (hh < 16) ? qw[d] : kw[d];
    float y = x * inv * w;

    __shared__ float sy[128];
    sy[d] = y;
    __syncthreads();
    float rot = (d < 64) ? -sy[d + 64] : sy[d - 64];
    float o = y * cosv[b * D + d] + rot * sinv[b * D + d];

    if (hh < 16) g_q[(b * NH + hh) * D + d] = o;
    else         out_k[(b * NKVH + (hh - 16)) * D + d] = o;
}

// ---------------- kernel 3: attention partials (flash decode) ------
// grid.x = B*NKVH (256), grid.y = chunk (16). 128 threads = 4 warps,
// warp covers 32 positions (exactly 2 KV blocks), unroll x8.
// K loads issue first; V loads deferred to overlap the shfl tree.
__global__ void attn_partial_kernel(const float* __restrict__ k_cache,
                                    const float* __restrict__ v_cache,
                                    const int* __restrict__ block_tables,
                                    const int* __restrict__ context_lens) {
    const int b = blockIdx.x >> 3;
    const int kvh = blockIdx.x & 7;
    const int chunk = blockIdx.y;
    const int ctx = context_lens[b];
    const int p0 = chunk * CHUNK;
    if (p0 >= ctx) return;
    const int pend = min(p0 + CHUNK, ctx);

    const int w = threadIdx.x >> 5;
    const int l = threadIdx.x & 31;
    const int wstart = p0 + w * 32;          // 32-aligned
    const int cnt = max(0, min(wstart + 32, pend) - wstart);

    // resolve the (at most) two KV blocks this warp touches
    const int* bt = block_tables + b * MAXBLK;
    const int bi = wstart >> 4;              // 0..126 (even)
    const int blk0 = max(0, __ldg(bt + bi));
    const int blk1 = max(0, __ldg(bt + min(bi + 1, MAXBLK - 1)));
    const long hoff = (long)kvh * D + 4 * l;
    const float* kb0 = k_cache + (long)blk0 * BLKSZ * NKVH * D + hoff;
    const float* kb1 = k_cache + (long)blk1 * BLKSZ * NKVH * D + hoff;
    const float* vb0 = v_cache + (long)blk0 * BLKSZ * NKVH * D + hoff;
    const float* vb1 = v_cache + (long)blk1 * BLKSZ * NKVH * D + hoff;
    const int rowstride = NKVH * D;          // 1024 floats per position

    const int h0 = kvh * NREP;
    const float4 q0 = *(const float4*)(g_q + (b * NH + h0) * D + 4 * l);
    const float4 q1 = *(const float4*)(g_q + (b * NH + h0 + 1) * D + 4 * l);
    const float scale = 0.08838834764831845f;

    float m0 = -CUDART_INF_F, l0 = 0.f, m1 = -CUDART_INF_F, l1 = 0.f;
    float4 a0 = {0.f, 0.f, 0.f, 0.f}, a1 = {0.f, 0.f, 0.f, 0.f};

    const int cnt8 = cnt & ~7;
    for (int i0 = 0; i0 < cnt8; i0 += 8) {
        const float* kb = (i0 < 16) ? kb0 : kb1;
        const float* vb = (i0 < 16) ? vb0 : vb1;
        const int s0off = (i0 & 8);          // slot base within block
        // phase 1: K loads + dot products
        float4 kv[8];
#pragma unroll
        for (int j = 0; j < 8; j++)
            kv[j] = *(const float4*)(kb + (s0off + j) * rowstride);
        float s0v[8], s1v[8];
#pragma unroll
        for (int j = 0; j < 8; j++) {
            s0v[j] = q0.x * kv[j].x + q0.y * kv[j].y + q0.z * kv[j].z + q0.w * kv[j].w;
            s1v[j] = q1.x * kv[j].x + q1.y * kv[j].y + q1.z * kv[j].z + q1.w * kv[j].w;
        }
        // phase 2: V loads issued now; latency hides under the shfl tree
        float4 vv[8];
#pragma unroll
        for (int j = 0; j < 8; j++)
            vv[j] = *(const float4*)(vb + (s0off + j) * rowstride);
#pragma unroll
        for (int o = 16; o > 0; o >>= 1) {
#pragma unroll
            for (int j = 0; j < 8; j++) {
                s0v[j] += __shfl_xor_sync(0xffffffffu, s0v[j], o);
                s1v[j] += __shfl_xor_sync(0xffffffffu, s1v[j], o);
            }
        }
#pragma unroll
        for (int j = 0; j < 8; j++) {
            float s0 = s0v[j] * scale, s1 = s1v[j] * scale;
            float nm0 = fmaxf(m0, s0);
            float e0 = __expf(s0 - nm0);
            float f0 = __expf(m0 - nm0);
            l0 = l0 * f0 + e0;
            a0.x = a0.x * f0 + e0 * vv[j].x; a0.y = a0.y * f0 + e0 * vv[j].y;
            a0.z = a0.z * f0 + e0 * vv[j].z; a0.w = a0.w * f0 + e0 * vv[j].w;
            m0 = nm0;

            float nm1 = fmaxf(m1, s1);
            float e1 = __expf(s1 - nm1);
            float f1 = __expf(m1 - nm1);
            l1 = l1 * f1 + e1;
            a1.x = a1.x * f1 + e1 * vv[j].x; a1.y = a1.y * f1 + e1 * vv[j].y;
            a1.z = a1.z * f1 + e1 * vv[j].z; a1.w = a1.w * f1 + e1 * vv[j].w;
            m1 = nm1;
        }
    }
    for (int i = cnt8; i < cnt; i++) {
        const float* kb = (i < 16) ? kb0 : kb1;
        const float* vb = (i < 16) ? vb0 : vb1;
        float4 kv = *(const float4*)(kb + (i & 15) * rowstride);
        float4 vv = *(const float4*)(vb + (i & 15) * rowstride);
        float s0 = q0.x * kv.x + q0.y * kv.y + q0.z * kv.z + q0.w * kv.w;
        float s1 = q1.x * kv.x + q1.y * kv.y + q1.z * kv.z + q1.w * kv.w;
#pragma unroll
        for (int o = 16; o > 0; o >>= 1) {
            s0 += __shfl_xor_sync(0xffffffffu, s0, o);
            s1 += __shfl_xor_sync(0xffffffffu, s1, o);
        }
        s0 *= scale; s1 *= scale;
        float nm0 = fmaxf(m0, s0);
        float e0 = __expf(s0 - nm0);
        float f0 = __expf(m0 - nm0);
        l0 = l0 * f0 + e0;
        a0.x = a0.x * f0 + e0 * vv.x; a0.y = a0.y * f0 + e0 * vv.y;
        a0.z = a0.z * f0 + e0 * vv.z; a0.w = a0.w * f0 + e0 * vv.w;
        m0 = nm0;
        float nm1 = fmaxf(m1, s1);
        float e1 = __expf(s1 - nm1);
        float f1 = __expf(m1 - nm1);
        l1 = l1 * f1 + e1;
        a1.x = a1.x * f1 + e1 * vv.x; a1.y = a1.y * f1 + e1 * vv.y;
        a1.z = a1.z * f1 + e1 * vv.z; a1.w = a1.w * f1 + e1 * vv.w;
        m1 = nm1;
    }

    // combine 4 warps in smem
    __shared__ float sml[4][2][2];
    __shared__ float sacc[4][2][128];
    *(float4*)&sacc[w][0][4 * l] = a0;
    *(float4*)&sacc[w][1][4 * l] = a1;
    if (l == 0) {
        sml[w][0][0] = m0; sml[w][0][1] = l0;
        sml[w][1][0] = m1; sml[w][1][1] = l1;
    }
    __syncthreads();

    const int d = threadIdx.x;
#pragma unroll
    for (int h = 0; h < 2; h++) {
        float M = fmaxf(fmaxf(sml[0][h][0], sml[1][h][0]),
                        fmaxf(sml[2][h][0], sml[3][h][0]));
        float L = 0.f, A = 0.f;
#pragma unroll
        for (int ww = 0; ww < 4; ww++) {
            float f = __expf(sml[ww][h][0] - M);
            L += sml[ww][h][1] * f;
            A += sacc[ww][h][d] * f;
        }
        long hi = (long)(b * NH + h0 + h) * NCHUNK + chunk;
        g_pacc[hi * 128 + d] = A;
        if (d == 0) g_ml[hi] = make_float2(M, L);
    }
}

// ---------------- kernel 4: combine chunk partials -----------------
// m/l loads are 16 contiguous float2s (one 128B line, L1-broadcast).
__global__ void attn_combine_kernel(const int* __restrict__ context_lens) {
    const int b = blockIdx.x >> 4;
    const int h = blockIdx.x & 15;
    const int d = threadIdx.x;
    const int ctx = context_lens[b];
    const int nch = (ctx + CHUNK - 1) / CHUNK;

    const long base = (long)(b * NH + h) * NCHUNK;
    float mv[NCHUNK], lv[NCHUNK], av[NCHUNK];
#pragma unroll
    for (int c = 0; c < NCHUNK; c++) {
        float2 ml = g_ml[base + c];
        mv[c] = (c < nch) ? ml.x : -CUDART_INF_F;
        lv[c] = ml.y;
        av[c] = g_pacc[(base + c) * 128 + d];
    }
    float M = -CUDART_INF_F;
#pragma unroll
    for (int c = 0; c < NCHUNK; c++) M = fmaxf(M, mv[c]);
    float L = 0.f, A = 0.f;
#pragma unroll
    for (int c = 0; c < NCHUNK; c++) {
        float f = __expf(mv[c] - M);
        L += lv[c] * f;
        A += av[c] * f;
    }
    g_attn[(b * NH + h) * D + d] = A / L;
}

// ---------------- kernel 5: wo projection (split-k=32, f32x2) ------
// grid = (16 tiles of 128 cols, 32 ks of 64) = 512 CTAs, 256 threads.
// Same per-warp k-stagger as gemm_qkv.
__global__ void gemm_wo_kernel(const float* __restrict__ W) {
    const int cg = threadIdx.x & 31;
    const int bg = threadIdx.x >> 5;
    const int col0 = blockIdx.x * 128 + cg * 4;
    const int ks = blockIdx.y;
    const int kb = ks * (HID / WO_KS);   // one 64-wide slab

    __shared__ u64t sXd[32][64];
    for (int i = threadIdx.x; i < 2048; i += 256) {
        int b = i >> 6, kk = i & 63;
        float x = g_attn[b * HID + kb + kk];
        sXd[b][kk] = pack2(x, x);
    }

    u64t acc01[4] = {0ull, 0ull, 0ull, 0ull};
    u64t acc23[4] = {0ull, 0ull, 0ull, 0ull};

    const int rot = bg * 8;              // per-warp k-order stagger

    __syncthreads();
    const float* wp = W + (long)kb * HID + col0;
#pragma unroll 8
    for (int kkx = 0; kkx < 64; kkx++) {
        int kk = (kkx + rot) & 63;
        ulonglong2 wv = *(const ulonglong2*)(wp + (long)kk * HID);
#pragma unroll
        for (int j = 0; j < 4; j++) {
            u64t xx = sXd[bg * 4 + j][kk];
            FMA2(acc01[j], wv.x, xx, acc01[j]);
            FMA2(acc23[j], wv.y, xx, acc23[j]);
        }
    }
#pragma unroll
    for (int j = 0; j < 4; j++) {
        ulonglong2 r; r.x = acc01[j]; r.y = acc23[j];
        *(ulonglong2*)(g_opart + ((long)ks * B + bg * 4 + j) * HID + col0) = r;
    }
}

// ---------------- kernel 6: finalize output ------------------------
__global__ void finalize_kernel(float* __restrict__ out) {
    int i = blockIdx.x * blockDim.x + threadIdx.x;  // 16384 float4s
    float4 r = {0.f, 0.f, 0.f, 0.f};
#pragma unroll
    for (int ks = 0; ks < WO_KS; ks++) {
        float4 a = ((const float4*)(g_opart + (long)ks * B * HID))[i];
        r.x += a.x; r.y += a.y; r.z += a.z; r.w += a.w;
    }
    ((float4*)out)[i] = r;
}

// ---------------- launch ------------------------------------------
extern "C" void kernel_launch(void* const* d_in, const int* in_sizes, int n_in,
                              void* d_out, int out_size) {
    const float* hidden = (const float*)d_in[0];
    const float* cosv   = (const float*)d_in[1];
    const float* sinv   = (const float*)d_in[2];
    const float* kcache = (const float*)d_in[3];
    const float* vcache = (const float*)d_in[4];
    const float* wq     = (const float*)d_in[5];
    const float* wk     = (const float*)d_in[6];
    const float* wv     = (const float*)d_in[7];
    const float* wo     = (const float*)d_in[8];
    const float* qnw    = (const float*)d_in[9];
    const float* knw    = (const float*)d_in[10];
    const int*   btab   = (const int*)d_in[11];
    const int*   clens  = (const int*)d_in[12];

    float* out    = (float*)d_out;
    float* out_k  = out + B * HID;
    float* out_v  = out_k + B * NKVH * D;

    gemm_qkv_kernel<<<dim3(32, QKV_KS), 256>>>(hidden, wq, wk, wv);
    norm_rope_kernel<<<dim3(B, 32), 128>>>(cosv, sinv, qnw, knw, out_k, out_v);
    attn_partial_kernel<<<dim3(B * NKVH, NCHUNK), 128>>>(kcache, vcache, btab, clens);
    attn_combine_kernel<<<B * NH, 128>>>(clens);
    gemm_wo_kernel<<<dim3(16, WO_KS), 256>>>(wo);
    finalize_kernel<<<64, 256>>>(out);
}

// round 16
// speedup vs baseline: 1.0223x; 1.0195x over previous
#include <cuda_runtime.h>
#include <cuda_bf16.h>
#include <math_constants.h>

#define B 32
#define HID 2048
#define D 128
#define NH 16
#define NKVH 8
#define NREP 2
#define BLKSZ 16
#define MAXBLK 128
#define CHUNK 128
#define NCHUNK 16
#define QKV_KS 16
#define WO_KS 32

typedef unsigned long long u64t;

// packed f32x2 fma: d = a*b + c elementwise on two packed floats
#define FMA2(d, a, b, c) \
    asm("fma.rn.f32x2 %0, %1, %2, %3;" : "=l"(d) : "l"(a), "l"(b), "l"(c))

__device__ __forceinline__ u64t pack2(float lo, float hi) {
    u64t r; asm("mov.b64 %0, {%1, %2};" : "=l"(r) : "f"(lo), "f"(hi)); return r;
}

// ---------------- scratch (no allocations allowed) ----------------
__device__ float g_qkvp[QKV_KS * B * 4096];        // qkv split-k partials
__device__ float g_q[B * NH * D];                  // post norm+rope q
__device__ float g_pacc[B * NH * NCHUNK * 128];    // per-chunk acc partials
__device__ float2 g_ml[B * NH * NCHUNK];           // per-chunk {m, l}
__device__ float g_attn[B * NH * D];               // attention output (pre-wo)
__device__ float g_opart[WO_KS * B * HID];         // wo split-k partials

// ---------------- kernel 1: qkv projection (split-k=16, f32x2) -----
// grid = (32 tiles of 128 cols, 16 k-slices of 128) = 512 CTAs, 256 thr.
// W loads batched 8-deep into explicit registers to force MLP=8.
__global__ void gemm_qkv_kernel(const float* __restrict__ X,
                                const float* __restrict__ Wq,
                                const float* __restrict__ Wk,
                                const float* __restrict__ Wv) {
    const int cg = threadIdx.x & 31;
    const int bg = threadIdx.x >> 5;
    const int gcol0 = blockIdx.x * 128 + cg * 4;
    const int ks = blockIdx.y;
    const int kbeg = ks * (HID / QKV_KS);   // 128-wide slice

    const float* W;
    int ldw, col0;
    if (gcol0 < 2048)      { W = Wq; ldw = 2048; col0 = gcol0; }
    else if (gcol0 < 3072) { W = Wk; ldw = 1024; col0 = gcol0 - 2048; }
    else                   { W = Wv; ldw = 1024; col0 = gcol0 - 3072; }

    __shared__ u64t sXd[32][64];   // x duplicated into both halves
    u64t acc01[4] = {0ull, 0ull, 0ull, 0ull};
    u64t acc23[4] = {0ull, 0ull, 0ull, 0ull};

    for (int kb = kbeg; kb < kbeg + HID / QKV_KS; kb += 64) {
        for (int i = threadIdx.x; i < 2048; i += 256) {
            int b = i >> 6, kk = i & 63;
            float x = X[b * HID + kb + kk];
            sXd[b][kk] = pack2(x, x);
        }
        __syncthreads();
        const float* wp = W + (long)kb * ldw + col0;
        for (int kk0 = 0; kk0 < 64; kk0 += 8) {
            // batch-load 8 W rows into registers (8 LDG.128 in flight)
            ulonglong2 wvv[8];
#pragma unroll
            for (int u = 0; u < 8; u++)
                wvv[u] = *(const ulonglong2*)(wp + (long)(kk0 + u) * ldw);
#pragma unroll
            for (int u = 0; u < 8; u++) {
#pragma unroll
                for (int j = 0; j < 4; j++) {
                    u64t xx = sXd[bg * 4 + j][kk0 + u];
                    FMA2(acc01[j], wvv[u].x, xx, acc01[j]);
                    FMA2(acc23[j], wvv[u].y, xx, acc23[j]);
                }
            }
        }
        __syncthreads();
    }
#pragma unroll
    for (int j = 0; j < 4; j++) {
        ulonglong2 r; r.x = acc01[j]; r.y = acc23[j];
        *(ulonglong2*)(g_qkvp + (long)ks * B * 4096 + (bg * 4 + j) * 4096 + gcol0) = r;
    }
}

// ---------------- kernel 2: reduce split-k + rmsnorm + rope --------
__global__ void norm_rope_kernel(const float* __restrict__ cosv,
                                 const float* __restrict__ sinv,
                                 const float* __restrict__ qw,
                                 const float* __restrict__ kw,
                                 float* __restrict__ out_k,
                                 float* __restrict__ out_v) {
    const int b = blockIdx.x;
    const int hh = blockIdx.y;
    const int d = threadIdx.x;

    int idx;
    if (hh < 16)       idx = b * 4096 + hh * 128 + d;
    else if (hh < 24)  idx = b * 4096 + 2048 + (hh - 16) * 128 + d;
    else               idx = b * 4096 + 3072 + (hh - 24) * 128 + d;

    float x = 0.f;
#pragma unroll
    for (int ks = 0; ks < QKV_KS; ks++) x += g_qkvp[(long)ks * B * 4096 + idx];

    if (hh >= 24) {
        out_v[(b * NKVH + (hh - 24)) * D + d] = x;
        return;
    }

    __shared__ float swarp[4];
    float s = x * x;
#pragma unroll
    for (int o = 16; o > 0; o >>= 1) s += __shfl_xor_sync(0xffffffffu, s, o);
    if ((d & 31) == 0) swarp[d >> 5] = s;
    __syncthreads();
    float tot = swarp[0] + swarp[1] + swarp[2] + swarp[3];
    float inv = rsqrtf(tot * (1.0f / 128.0f) + 1e-6f);
    float w = (hh < 16) ? qw[d] : kw[d];
    float y = x * inv * w;

    __shared__ float sy[128];
    sy[d] = y;
    __syncthreads();
    float rot = (d < 64) ? -sy[d + 64] : sy[d - 64];
    float o = y * cosv[b * D + d] + rot * sinv[b * D + d];

    if (hh < 16) g_q[(b * NH + hh) * D + d] = o;
    else         out_k[(b * NKVH + (hh - 16)) * D + d] = o;
}

// ---------------- kernel 3: attention partials (flash decode) ------
// grid.x = B*NKVH (256), grid.y = chunk (16). 128 threads = 4 warps,
// warp covers 32 positions (exactly 2 KV blocks), unroll x8.
// K loads issue first; V loads deferred to overlap the shfl tree.
__global__ void attn_partial_kernel(const float* __restrict__ k_cache,
                                    const float* __restrict__ v_cache,
                                    const int* __restrict__ block_tables,
                                    const int* __restrict__ context_lens) {
    const int b = blockIdx.x >> 3;
    const int kvh = blockIdx.x & 7;
    const int chunk = blockIdx.y;
    const int ctx = context_lens[b];
    const int p0 = chunk * CHUNK;
    if (p0 >= ctx) return;
    const int pend = min(p0 + CHUNK, ctx);

    const int w = threadIdx.x >> 5;
    const int l = threadIdx.x & 31;
    const int wstart = p0 + w * 32;          // 32-aligned
    const int cnt = max(0, min(wstart + 32, pend) - wstart);

    // resolve the (at most) two KV blocks this warp touches
    const int* bt = block_tables + b * MAXBLK;
    const int bi = wstart >> 4;              // 0..126 (even)
    const int blk0 = max(0, __ldg(bt + bi));
    const int blk1 = max(0, __ldg(bt + min(bi + 1, MAXBLK - 1)));
    const long hoff = (long)kvh * D + 4 * l;
    const float* kb0 = k_cache + (long)blk0 * BLKSZ * NKVH * D + hoff;
    const float* kb1 = k_cache + (long)blk1 * BLKSZ * NKVH * D + hoff;
    const float* vb0 = v_cache + (long)blk0 * BLKSZ * NKVH * D + hoff;
    const float* vb1 = v_cache + (long)blk1 * BLKSZ * NKVH * D + hoff;
    const int rowstride = NKVH * D;          // 1024 floats per position

    const int h0 = kvh * NREP;
    const float4 q0 = *(const float4*)(g_q + (b * NH + h0) * D + 4 * l);
    const float4 q1 = *(const float4*)(g_q + (b * NH + h0 + 1) * D + 4 * l);
    const float scale = 0.08838834764831845f;

    float m0 = -CUDART_INF_F, l0 = 0.f, m1 = -CUDART_INF_F, l1 = 0.f;
    float4 a0 = {0.f, 0.f, 0.f, 0.f}, a1 = {0.f, 0.f, 0.f, 0.f};

    const int cnt8 = cnt & ~7;
    for (int i0 = 0; i0 < cnt8; i0 += 8) {
        const float* kb = (i0 < 16) ? kb0 : kb1;
        const float* vb = (i0 < 16) ? vb0 : vb1;
        const int s0off = (i0 & 8);          // slot base within block
        // phase 1: K loads + dot products
        float4 kv[8];
#pragma unroll
        for (int j = 0; j < 8; j++)
            kv[j] = *(const float4*)(kb + (s0off + j) * rowstride);
        float s0v[8], s1v[8];
#pragma unroll
        for (int j = 0; j < 8; j++) {
            s0v[j] = q0.x * kv[j].x + q0.y * kv[j].y + q0.z * kv[j].z + q0.w * kv[j].w;
            s1v[j] = q1.x * kv[j].x + q1.y * kv[j].y + q1.z * kv[j].z + q1.w * kv[j].w;
        }
        // phase 2: V loads issued now; latency hides under the shfl tree
        float4 vv[8];
#pragma unroll
        for (int j = 0; j < 8; j++)
            vv[j] = *(const float4*)(vb + (s0off + j) * rowstride);
#pragma unroll
        for (int o = 16; o > 0; o >>= 1) {
#pragma unroll
            for (int j = 0; j < 8; j++) {
                s0v[j] += __shfl_xor_sync(0xffffffffu, s0v[j], o);
                s1v[j] += __shfl_xor_sync(0xffffffffu, s1v[j], o);
            }
        }
#pragma unroll
        for (int j = 0; j < 8; j++) {
            float s0 = s0v[j] * scale, s1 = s1v[j] * scale;
            float nm0 = fmaxf(m0, s0);
            float e0 = __expf(s0 - nm0);
            float f0 = __expf(m0 - nm0);
            l0 = l0 * f0 + e0;
            a0.x = a0.x * f0 + e0 * vv[j].x; a0.y = a0.y * f0 + e0 * vv[j].y;
            a0.z = a0.z * f0 + e0 * vv[j].z; a0.w = a0.w * f0 + e0 * vv[j].w;
            m0 = nm0;

            float nm1 = fmaxf(m1, s1);
            float e1 = __expf(s1 - nm1);
            float f1 = __expf(m1 - nm1);
            l1 = l1 * f1 + e1;
            a1.x = a1.x * f1 + e1 * vv[j].x; a1.y = a1.y * f1 + e1 * vv[j].y;
            a1.z = a1.z * f1 + e1 * vv[j].z; a1.w = a1.w * f1 + e1 * vv[j].w;
            m1 = nm1;
        }
    }
    for (int i = cnt8; i < cnt; i++) {
        const float* kb = (i < 16) ? kb0 : kb1;
        const float* vb = (i < 16) ? vb0 : vb1;
        float4 kv = *(const float4*)(kb + (i & 15) * rowstride);
        float4 vv = *(const float4*)(vb + (i & 15) * rowstride);
        float s0 = q0.x * kv.x + q0.y * kv.y + q0.z * kv.z + q0.w * kv.w;
        float s1 = q1.x * kv.x + q1.y * kv.y + q1.z * kv.z + q1.w * kv.w;
#pragma unroll
        for (int o = 16; o > 0; o >>= 1) {
            s0 += __shfl_xor_sync(0xffffffffu, s0, o);
            s1 += __shfl_xor_sync(0xffffffffu, s1, o);
        }
        s0 *= scale; s1 *= scale;
        float nm0 = fmaxf(m0, s0);
        float e0 = __expf(s0 - nm0);
        float f0 = __expf(m0 - nm0);
        l0 = l0 * f0 + e0;
        a0.x = a0.x * f0 + e0 * vv.x; a0.y = a0.y * f0 + e0 * vv.y;
        a0.z = a0.z * f0 + e0 * vv.z; a0.w = a0.w * f0 + e0 * vv.w;
        m0 = nm0;
        float nm1 = fmaxf(m1, s1);
        float e1 = __expf(s1 - nm1);
        float f1 = __expf(m1 - nm1);
        l1 = l1 * f1 + e1;
        a1.x = a1.x * f1 + e1 * vv.x; a1.y = a1.y * f1 + e1 * vv.y;
        a1.z = a1.z * f1 + e1 * vv.z; a1.w = a1.w * f1 + e1 * vv.w;
        m1 = nm1;
    }

    // combine 4 warps in smem
    __shared__ float sml[4][2][2];
    __shared__ float sacc[4][2][128];
    *(float4*)&sacc[w][0][4 * l] = a0;
    *(float4*)&sacc[w][1][4 * l] = a1;
    if (l == 0) {
        sml[w][0][0] = m0; sml[w][0][1] = l0;
        sml[w][1][0] = m1; sml[w][1][1] = l1;
    }
    __syncthreads();

    const int d = threadIdx.x;
#pragma unroll
    for (int h = 0; h < 2; h++) {
        float M = fmaxf(fmaxf(sml[0][h][0], sml[1][h][0]),
                        fmaxf(sml[2][h][0], sml[3][h][0]));
        float L = 0.f, A = 0.f;
#pragma unroll
        for (int ww = 0; ww < 4; ww++) {
            float f = __expf(sml[ww][h][0] - M);
            L += sml[ww][h][1] * f;
            A += sacc[ww][h][d] * f;
        }
        long hi = (long)(b * NH + h0 + h) * NCHUNK + chunk;
        g_pacc[hi * 128 + d] = A;
        if (d == 0) g_ml[hi] = make_float2(M, L);
    }
}

// ---------------- kernel 4: combine chunk partials -----------------
// m/l loads are 16 contiguous float2s (one 128B line, L1-broadcast).
__global__ void attn_combine_kernel(const int* __restrict__ context_lens) {
    const int b = blockIdx.x >> 4;
    const int h = blockIdx.x & 15;
    const int d = threadIdx.x;
    const int ctx = context_lens[b];
    const int nch = (ctx + CHUNK - 1) / CHUNK;

    const long base = (long)(b * NH + h) * NCHUNK;
    float mv[NCHUNK], lv[NCHUNK], av[NCHUNK];
#pragma unroll
    for (int c = 0; c < NCHUNK; c++) {
        float2 ml = g_ml[base + c];
        mv[c] = (c < nch) ? ml.x : -CUDART_INF_F;
        lv[c] = ml.y;
        av[c] = g_pacc[(base + c) * 128 + d];
    }
    float M = -CUDART_INF_F;
#pragma unroll
    for (int c = 0; c < NCHUNK; c++) M = fmaxf(M, mv[c]);
    float L = 0.f, A = 0.f;
#pragma unroll
    for (int c = 0; c < NCHUNK; c++) {
        float f = __expf(mv[c] - M);
        L += lv[c] * f;
        A += av[c] * f;
    }
    g_attn[(b * NH + h) * D + d] = A / L;
}

// ---------------- kernel 5: wo projection (split-k=32, f32x2) ------
// grid = (16 tiles of 128 cols, 32 ks of 64) = 512 CTAs, 256 threads.
// W loads batched 8-deep into explicit registers to force MLP=8.
__global__ void gemm_wo_kernel(const float* __restrict__ W) {
    const int cg = threadIdx.x & 31;
    const int bg = threadIdx.x >> 5;
    const int col0 = blockIdx.x * 128 + cg * 4;
    const int ks = blockIdx.y;
    const int kb = ks * (HID / WO_KS);   // one 64-wide slab

    __shared__ u64t sXd[32][64];
    for (int i = threadIdx.x; i < 2048; i += 256) {
        int b = i >> 6, kk = i & 63;
        float x = g_attn[b * HID + kb + kk];
        sXd[b][kk] = pack2(x, x);
    }

    u64t acc01[4] = {0ull, 0ull, 0ull, 0ull};
    u64t acc23[4] = {0ull, 0ull, 0ull, 0ull};

    __syncthreads();
    const float* wp = W + (long)kb * HID + col0;
    for (int kk0 = 0; kk0 < 64; kk0 += 8) {
        ulonglong2 wvv[8];
#pragma unroll
        for (int u = 0; u < 8; u++)
            wvv[u] = *(const ulonglong2*)(wp + (long)(kk0 + u) * HID);
#pragma unroll
        for (int u = 0; u < 8; u++) {
#pragma unroll
            for (int j = 0; j < 4; j++) {
                u64t xx = sXd[bg * 4 + j][kk0 + u];
                FMA2(acc01[j], wvv[u].x, xx, acc01[j]);
                FMA2(acc23[j], wvv[u].y, xx, acc23[j]);
            }
        }
    }
#pragma unroll
    for (int j = 0; j < 4; j++) {
        ulonglong2 r; r.x = acc01[j]; r.y = acc23[j];
        *(ulonglong2*)(g_opart + ((long)ks * B + bg * 4 + j) * HID + col0) = r;
    }
}

// ---------------- kernel 6: finalize output ------------------------
__global__ void finalize_kernel(float* __restrict__ out) {
    int i = blockIdx.x * blockDim.x + threadIdx.x;  // 16384 float4s
    float4 r = {0.f, 0.f, 0.f, 0.f};
#pragma unroll
    for (int ks = 0; ks < WO_KS; ks++) {
        float4 a = ((const float4*)(g_opart + (long)ks * B * HID))[i];
        r.x += a.x; r.y += a.y; r.z += a.z; r.w += a.w;
    }
    ((float4*)out)[i] = r;
}

// ---------------- launch ------------------------------------------
extern "C" void kernel_launch(void* const* d_in, const int* in_sizes, int n_in,
                              void* d_out, int out_size) {
    const float* hidden = (const float*)d_in[0];
    const float* cosv   = (const float*)d_in[1];
    const float* sinv   = (const float*)d_in[2];
    const float* kcache = (const float*)d_in[3];
    const float* vcache = (const float*)d_in[4];
    const float* wq     = (const float*)d_in[5];
    const float* wk     = (const float*)d_in[6];
    const float* wv     = (const float*)d_in[7];
    const float* wo     = (const float*)d_in[8];
    const float* qnw    = (const float*)d_in[9];
    const float* knw    = (const float*)d_in[10];
    const int*   btab   = (const int*)d_in[11];
    const int*   clens  = (const int*)d_in[12];

    float* out    = (float*)d_out;
    float* out_k  = out + B * HID;
    float* out_v  = out_k + B * NKVH * D;

    gemm_qkv_kernel<<<dim3(32, QKV_KS), 256>>>(hidden, wq, wk, wv);
    norm_rope_kernel<<<dim3(B, 32), 128>>>(cosv, sinv, qnw, knw, out_k, out_v);
    attn_partial_kernel<<<dim3(B * NKVH, NCHUNK), 128>>>(kcache, vcache, btab, clens);
    attn_combine_kernel<<<B * NH, 128>>>(clens);
    gemm_wo_kernel<<<dim3(16, WO_KS), 256>>>(wo);
    finalize_kernel<<<64, 256>>>(out);
}